// round 1
// baseline (speedup 1.0000x reference)
#include <cuda_runtime.h>
#include <math.h>

#define NT   45
#define BB   32768
#define HID  64
#define TBL  65536
#define K1_BLOCKS (BB/128)            // 256
#define K3_BLOCKS ((NT*BB)/256)       // 5760

// ---------------- device scratch (static, no allocation) ----------------
__device__ float    g_zs[NT*BB];          // 5.9 MB latent path
__device__ float    g_table[TBL+1];       // P(z) lookup table
__device__ unsigned g_zmin_u, g_zmax_u;   // ordered-uint encoded range
__device__ float    g_part_li[K1_BLOCKS];
__device__ float    g_part_kl[K1_BLOCKS];
__device__ float    g_part_logp[K3_BLOCKS];

// monotone float <-> uint mapping for atomicMin/Max on floats
__device__ __forceinline__ unsigned f2ord(float f) {
    unsigned u = __float_as_uint(f);
    return (u & 0x80000000u) ? ~u : (u | 0x80000000u);
}
__device__ __forceinline__ float ord2f(unsigned u) {
    u = (u & 0x80000000u) ? (u ^ 0x80000000u) : ~u;
    return __uint_as_float(u);
}

// ---------------- K0: reset per-launch state (graph replays!) -----------
__global__ void k_init() {
    g_zmin_u = 0xFFFFFFFFu;
    g_zmax_u = 0u;
}

// ---------------- K1: encoder + posterior + SDE scan --------------------
__global__ void __launch_bounds__(128) k_scan(
    const float* __restrict__ xs,  const float* __restrict__ ts,
    const float* __restrict__ eps0,const float* __restrict__ bm,
    const float* __restrict__ ew1, const float* __restrict__ eb1,
    const float* __restrict__ ew2, const float* __restrict__ eb2,
    const float* __restrict__ qw,  const float* __restrict__ qb,
    const float* __restrict__ fw1, const float* __restrict__ fb1,
    const float* __restrict__ fw2, const float* __restrict__ fb2,
    const float* __restrict__ pz0m,const float* __restrict__ pz0ls,
    const float* __restrict__ kap, const float* __restrict__ the,
    const float* __restrict__ sig)
{
    __shared__ float4 sE[HID];    // {enc_w1, enc_b1, enc_w2[:,0], enc_w2[:,1]}
    __shared__ float4 sF[HID];    // {f_w1[0], f_w1[1], f_w1[2], f_b1}
    __shared__ float  sW2[HID];   // f_w2
    __shared__ float  sTs[NT];
    __shared__ float  sred[8];

    const int t = threadIdx.x;
    if (t < HID) {
        sE[t]  = make_float4(ew1[t], eb1[t], ew2[2*t], ew2[2*t+1]);
        sF[t]  = make_float4(fw1[t], fw1[HID+t], fw1[2*HID+t], fb1[t]);
        sW2[t] = fw2[t];
    }
    if (t < NT) sTs[t] = ts[t];
    __syncthreads();

    const int b = blockIdx.x * 128 + t;

    const float eb2_0 = eb2[0], eb2_1 = eb2[1];
    const float fb2_s = fb2[0];
    const float kappa = kap[0], theta = the[0], sigma = sig[0];
    const float inv_sig = 1.0f / sigma;
    const float pm = pz0m[0], pls = pz0ls[0];

    // --- encoder at n = 0 ---
    float x0 = xs[b];
    float c0 = eb2_0, c1 = eb2_1;
    #pragma unroll
    for (int j = 0; j < HID; j++) {
        float4 e = sE[j];
        float h = fmaxf(fmaf(x0, e.x, e.y), 0.0f);
        c0 = fmaf(h, e.z, c0);
        c1 = fmaf(h, e.w, c1);
    }
    // q = ctx0 @ qz0_w + qz0_b ; qm = q[:,0], qls = q[:,1]
    float qm  = fmaf(c0, qw[0], fmaf(c1, qw[2], qb[0]));
    float qls = fmaf(c0, qw[1], fmaf(c1, qw[3], qb[1]));

    float z = qm + expf(qls) * eps0[b];

    // KL(q(z0) || p(z0))
    float dqm = qm - pm;
    float kl  = pls - qls
              + (expf(2.0f*qls) + dqm*dqm) / (2.0f * expf(2.0f*pls))
              - 0.5f;

    g_zs[b] = z;
    float zmn = z, zmx = z;
    float li = 0.0f;

    #pragma unroll 1
    for (int n = 1; n < NT; n++) {
        float dt  = sTs[n] - sTs[n-1];
        float x   = xs[n*BB + b];

        // encoder ctx[n]
        float cc0 = eb2_0, cc1 = eb2_1;
        #pragma unroll
        for (int j = 0; j < HID; j++) {
            float4 e = sE[j];
            float h = fmaxf(fmaf(x, e.x, e.y), 0.0f);
            cc0 = fmaf(h, e.z, cc0);
            cc1 = fmaf(h, e.w, cc1);
        }

        // drift f([z, c0, c1])
        float f = fb2_s;
        #pragma unroll
        for (int j = 0; j < HID; j++) {
            float4 w = sF[j];
            float h = fmaf(z, w.x, fmaf(cc0, w.y, fmaf(cc1, w.z, w.w)));
            h = fmaxf(h, 0.0f);
            f = fmaf(h, sW2[j], f);
        }

        float u = (f - kappa * (theta - z)) * inv_sig;
        li = fmaf(0.5f * u * u, dt, li);

        float dw = bm[(n-1)*BB + b] * sqrtf(dt);
        z = fmaf(f, dt, fmaf(sigma, dw, z));

        g_zs[n*BB + b] = z;
        zmn = fminf(zmn, z);
        zmx = fmaxf(zmx, z);
    }

    // range: order-invariant -> atomics fine
    #pragma unroll
    for (int o = 16; o; o >>= 1) {
        zmn = fminf(zmn, __shfl_xor_sync(0xffffffffu, zmn, o));
        zmx = fmaxf(zmx, __shfl_xor_sync(0xffffffffu, zmx, o));
    }
    if ((t & 31) == 0) {
        atomicMin(&g_zmin_u, f2ord(zmn));
        atomicMax(&g_zmax_u, f2ord(zmx));
    }

    // deterministic fixed-order reductions of li and kl
    float vli = li, vkl = kl;
    #pragma unroll
    for (int o = 16; o; o >>= 1) {
        vli += __shfl_xor_sync(0xffffffffu, vli, o);
        vkl += __shfl_xor_sync(0xffffffffu, vkl, o);
    }
    int w = t >> 5, l = t & 31;
    if (l == 0) sred[w] = vli;
    __syncthreads();
    if (t == 0) {
        float s = sred[0] + sred[1] + sred[2] + sred[3];
        g_part_li[blockIdx.x] = s;
    }
    __syncthreads();
    if (l == 0) sred[w] = vkl;
    __syncthreads();
    if (t == 0) {
        float s = sred[0] + sred[1] + sred[2] + sred[3];
        g_part_kl[blockIdx.x] = s;
    }
}

// ---------------- K2: tabulate P(z) = proj MLP of scalar z --------------
__global__ void __launch_bounds__(128) k_table(
    const float* __restrict__ pw1, const float* __restrict__ pb1,
    const float* __restrict__ pW2, const float* __restrict__ pb2,
    const float* __restrict__ pw3, const float* __restrict__ pb3)
{
    __shared__ float sw1[HID], sb1[HID], sb2[HID], sw3[HID];
    __shared__ float sW2[HID*HID];

    const int t = threadIdx.x;
    if (t < HID) { sw1[t]=pw1[t]; sb1[t]=pb1[t]; sb2[t]=pb2[t]; sw3[t]=pw3[t]; }
    for (int i = t; i < HID*HID; i += 128) sW2[i] = pW2[i];
    __syncthreads();

    const int i = blockIdx.x * 128 + t;
    if (i > TBL) return;

    float zmin = ord2f(g_zmin_u), zmax = ord2f(g_zmax_u);
    float z = zmin + (zmax - zmin) * ((float)i / (float)TBL);

    // h1 = softplus(z*w1 + b1)
    float h1[HID];
    #pragma unroll 8
    for (int j = 0; j < HID; j++) {
        float a = fmaf(z, sw1[j], sb1[j]);
        h1[j] = fmaxf(a, 0.0f) + log1pf(expf(-fabsf(a)));
    }

    float acc = pb3[0];
    #pragma unroll 1
    for (int kt = 0; kt < 4; kt++) {
        float h2[16];
        #pragma unroll
        for (int k = 0; k < 16; k++) h2[k] = sb2[kt*16 + k];
        #pragma unroll 8
        for (int j = 0; j < HID; j++) {
            float hj = h1[j];
            #pragma unroll
            for (int k = 0; k < 16; k++)
                h2[k] = fmaf(hj, sW2[j*HID + kt*16 + k], h2[k]);
        }
        #pragma unroll
        for (int k = 0; k < 16; k++)
            acc = fmaf(fmaxf(h2[k], 0.0f), sw3[kt*16 + k], acc);
    }
    g_table[i] = acc;
}

// ---------------- K3: table lookup -> _xs + logp partials ---------------
__global__ void __launch_bounds__(256) k_proj(
    const float* __restrict__ xs, const float* __restrict__ nstd,
    float* __restrict__ out)
{
    const int i = blockIdx.x * 256 + threadIdx.x;

    float zmin = ord2f(g_zmin_u), zmax = ord2f(g_zmax_u);
    float inv_h = (float)TBL / (zmax - zmin);

    float z  = g_zs[i];
    float tt = (z - zmin) * inv_h;
    tt = fminf(fmaxf(tt, 0.0f), (float)TBL);
    int   j  = min((int)tt, TBL - 1);
    float fr = tt - (float)j;
    float v0 = g_table[j];
    float v1 = g_table[j+1];
    float xh = fmaf(v1 - v0, fr, v0);

    out[2 + i] = xh;

    float std = nstd[0];
    float r = (xs[i] - xh) / std;
    float logp = fmaf(-0.5f, r*r, -logf(std) - 0.91893853320467274f); // 0.5*log(2pi)

    // deterministic block reduce
    float v = logp;
    #pragma unroll
    for (int o = 16; o; o >>= 1) v += __shfl_xor_sync(0xffffffffu, v, o);
    __shared__ float sred[8];
    int w = threadIdx.x >> 5, l = threadIdx.x & 31;
    if (l == 0) sred[w] = v;
    __syncthreads();
    if (threadIdx.x == 0) {
        float s = 0.0f;
        #pragma unroll
        for (int k = 0; k < 8; k++) s += sred[k];
        g_part_logp[blockIdx.x] = s;
    }
}

// ---------------- K4: final deterministic reduction ----------------------
__global__ void __launch_bounds__(256) k_final(float* __restrict__ out)
{
    __shared__ double s[256];
    const int t = threadIdx.x;

    // logp
    double a = 0.0;
    for (int i = t; i < K3_BLOCKS; i += 256) a += (double)g_part_logp[i];
    s[t] = a; __syncthreads();
    for (int o = 128; o; o >>= 1) { if (t < o) s[t] += s[t+o]; __syncthreads(); }
    double logp_sum = s[0];
    __syncthreads();

    // kl
    s[t] = (t < K1_BLOCKS) ? (double)g_part_kl[t] : 0.0; __syncthreads();
    for (int o = 128; o; o >>= 1) { if (t < o) s[t] += s[t+o]; __syncthreads(); }
    double kl_sum = s[0];
    __syncthreads();

    // li
    s[t] = (t < K1_BLOCKS) ? (double)g_part_li[t] : 0.0; __syncthreads();
    for (int o = 128; o; o >>= 1) { if (t < o) s[t] += s[t+o]; __syncthreads(); }
    double li_sum = s[0];

    if (t == 0) {
        out[0] = (float)(logp_sum / (double)BB);
        out[1] = (float)((kl_sum + li_sum) / (double)BB);
    }
}

// ---------------- launch ----------------
extern "C" void kernel_launch(void* const* d_in, const int* in_sizes, int n_in,
                              void* d_out, int out_size)
{
    const float* xs    = (const float*)d_in[0];
    const float* ts    = (const float*)d_in[1];
    const float* nstd  = (const float*)d_in[2];
    const float* eps0  = (const float*)d_in[3];
    const float* bm    = (const float*)d_in[4];
    const float* ew1   = (const float*)d_in[5];
    const float* eb1   = (const float*)d_in[6];
    const float* ew2   = (const float*)d_in[7];
    const float* eb2   = (const float*)d_in[8];
    const float* qw    = (const float*)d_in[9];
    const float* qb    = (const float*)d_in[10];
    const float* fw1   = (const float*)d_in[11];
    const float* fb1   = (const float*)d_in[12];
    const float* fw2   = (const float*)d_in[13];
    const float* fb2   = (const float*)d_in[14];
    const float* pw1   = (const float*)d_in[15];
    const float* pb1   = (const float*)d_in[16];
    const float* pW2   = (const float*)d_in[17];
    const float* pb2   = (const float*)d_in[18];
    const float* pw3   = (const float*)d_in[19];
    const float* pb3   = (const float*)d_in[20];
    const float* pz0m  = (const float*)d_in[21];
    const float* pz0ls = (const float*)d_in[22];
    const float* kap   = (const float*)d_in[23];
    const float* the   = (const float*)d_in[24];
    const float* sig   = (const float*)d_in[25];

    float* out = (float*)d_out;

    k_init<<<1, 1>>>();
    k_scan<<<K1_BLOCKS, 128>>>(xs, ts, eps0, bm,
                               ew1, eb1, ew2, eb2, qw, qb,
                               fw1, fb1, fw2, fb2,
                               pz0m, pz0ls, kap, the, sig);
    k_table<<<(TBL + 1 + 127) / 128, 128>>>(pw1, pb1, pW2, pb2, pw3, pb3);
    k_proj<<<K3_BLOCKS, 256>>>(xs, nstd, out);
    k_final<<<1, 256>>>(out);
}

// round 4
// speedup vs baseline: 1.8249x; 1.8249x over previous
#include <cuda_runtime.h>
#include <math.h>

#define NT   45
#define BB   32768
#define HID  64
#define TBL  16384
#define K1_BLOCKS (BB/128)            // 256
#define K3_BLOCKS ((NT*BB)/(256*4))   // 1440

// ---------------- device scratch (static, no allocation) ----------------
__device__ float    g_zs[NT*BB];          // 5.9 MB latent path
__device__ float    g_table[TBL+1];       // P(z) lookup table
__device__ unsigned g_zmin_u, g_zmax_u;   // ordered-uint encoded range
__device__ float    g_part_li[K1_BLOCKS];
__device__ float    g_part_kl[K1_BLOCKS];
__device__ float    g_part_logp[K3_BLOCKS];

// monotone float <-> uint mapping for atomicMin/Max on floats
__device__ __forceinline__ unsigned f2ord(float f) {
    unsigned u = __float_as_uint(f);
    return (u & 0x80000000u) ? ~u : (u | 0x80000000u);
}
__device__ __forceinline__ float ord2f(unsigned u) {
    u = (u & 0x80000000u) ? (u ^ 0x80000000u) : ~u;
    return __uint_as_float(u);
}

// ---------------- K0: reset per-launch state (graph replays!) -----------
__global__ void k_init() {
    g_zmin_u = 0xFFFFFFFFu;
    g_zmax_u = 0u;
}

// ---------------- K1: encoder + posterior + SDE scan --------------------
// NOTE: numerics here are kept bit-identical to the R1 kernel that passed
// with rel_err 1.4e-6 (the scan is chaotic; dt=1 amplifies perturbations).
__global__ void __launch_bounds__(128) k_scan(
    const float* __restrict__ xs,  const float* __restrict__ ts,
    const float* __restrict__ eps0,const float* __restrict__ bm,
    const float* __restrict__ ew1, const float* __restrict__ eb1,
    const float* __restrict__ ew2, const float* __restrict__ eb2,
    const float* __restrict__ qw,  const float* __restrict__ qb,
    const float* __restrict__ fw1, const float* __restrict__ fb1,
    const float* __restrict__ fw2, const float* __restrict__ fb2,
    const float* __restrict__ pz0m,const float* __restrict__ pz0ls,
    const float* __restrict__ kap, const float* __restrict__ the,
    const float* __restrict__ sig)
{
    __shared__ float4 sE[HID];    // {enc_w1, enc_b1, enc_w2[:,0], enc_w2[:,1]}
    __shared__ float4 sF[HID];    // {f_w1[0], f_w1[1], f_w1[2], f_b1}
    __shared__ float  sW2[HID];   // f_w2
    __shared__ float  sTs[NT];
    __shared__ float  sred[4];

    const int t = threadIdx.x;
    if (t < HID) {
        sE[t]  = make_float4(ew1[t], eb1[t], ew2[2*t], ew2[2*t+1]);
        sF[t]  = make_float4(fw1[t], fw1[HID+t], fw1[2*HID+t], fb1[t]);
        sW2[t] = fw2[t];
    }
    if (t < NT) sTs[t] = ts[t];
    __syncthreads();

    const int b = blockIdx.x * 128 + t;

    const float eb2_0 = eb2[0], eb2_1 = eb2[1];
    const float fb2_s = fb2[0];
    const float kappa = kap[0], theta = the[0], sigma = sig[0];
    const float inv_sig = 1.0f / sigma;
    const float pm = pz0m[0], pls = pz0ls[0];

    // --- encoder at n = 0 ---
    float x0 = xs[b];
    float c0 = eb2_0, c1 = eb2_1;
    #pragma unroll
    for (int j = 0; j < HID; j++) {
        float4 e = sE[j];
        float h = fmaxf(fmaf(x0, e.x, e.y), 0.0f);
        c0 = fmaf(h, e.z, c0);
        c1 = fmaf(h, e.w, c1);
    }
    float qm  = fmaf(c0, qw[0], fmaf(c1, qw[2], qb[0]));
    float qls = fmaf(c0, qw[1], fmaf(c1, qw[3], qb[1]));

    float z = qm + expf(qls) * eps0[b];

    float dqm = qm - pm;
    float kl  = pls - qls
              + (expf(2.0f*qls) + dqm*dqm) / (2.0f * expf(2.0f*pls))
              - 0.5f;

    g_zs[b] = z;
    float zmn = z, zmx = z;
    float li = 0.0f;

    float xn  = xs[BB + b];   // prefetch (timing only; values identical)
    float bmv = bm[b];

    #pragma unroll 1
    for (int n = 1; n < NT; n++) {
        const float x = xn, dwe = bmv;
        if (n + 1 < NT) { xn = xs[(n+1)*BB + b]; bmv = bm[n*BB + b]; }
        const float dt = sTs[n] - sTs[n-1];

        // encoder ctx[n]  (identical op sequence to R1)
        float cc0 = eb2_0, cc1 = eb2_1;
        #pragma unroll
        for (int j = 0; j < HID; j++) {
            float4 e = sE[j];
            float h = fmaxf(fmaf(x, e.x, e.y), 0.0f);
            cc0 = fmaf(h, e.z, cc0);
            cc1 = fmaf(h, e.w, cc1);
        }

        // drift f([z, c0, c1])  (identical op sequence to R1)
        float f = fb2_s;
        #pragma unroll
        for (int j = 0; j < HID; j++) {
            float4 w = sF[j];
            float h = fmaf(z, w.x, fmaf(cc0, w.y, fmaf(cc1, w.z, w.w)));
            h = fmaxf(h, 0.0f);
            f = fmaf(h, sW2[j], f);
        }

        float u = (f - kappa * (theta - z)) * inv_sig;
        li = fmaf(0.5f * u * u, dt, li);

        float dw = dwe * sqrtf(dt);
        z = fmaf(f, dt, fmaf(sigma, dw, z));

        g_zs[n*BB + b] = z;
        zmn = fminf(zmn, z);
        zmx = fmaxf(zmx, z);
    }

    // range: order-invariant -> atomics fine
    #pragma unroll
    for (int o = 16; o; o >>= 1) {
        zmn = fminf(zmn, __shfl_xor_sync(0xffffffffu, zmn, o));
        zmx = fmaxf(zmx, __shfl_xor_sync(0xffffffffu, zmx, o));
    }
    if ((t & 31) == 0) {
        atomicMin(&g_zmin_u, f2ord(zmn));
        atomicMax(&g_zmax_u, f2ord(zmx));
    }

    // deterministic fixed-order reductions
    float vli = li, vkl = kl;
    #pragma unroll
    for (int o = 16; o; o >>= 1) {
        vli += __shfl_xor_sync(0xffffffffu, vli, o);
        vkl += __shfl_xor_sync(0xffffffffu, vkl, o);
    }
    int w = t >> 5, l = t & 31;
    if (l == 0) sred[w] = vli;
    __syncthreads();
    if (t == 0) g_part_li[blockIdx.x] = (sred[0]+sred[1])+(sred[2]+sred[3]);
    __syncthreads();
    if (l == 0) sred[w] = vkl;
    __syncthreads();
    if (t == 0) g_part_kl[blockIdx.x] = (sred[0]+sred[1])+(sred[2]+sred[3]);
}

// ---------------- K2: tabulate P(z) (full unroll, registers only) -------
__global__ void __launch_bounds__(128) k_table(
    const float* __restrict__ pw1, const float* __restrict__ pb1,
    const float* __restrict__ pW2, const float* __restrict__ pb2,
    const float* __restrict__ pw3, const float* __restrict__ pb3)
{
    __shared__ float sw1[HID], sb1[HID], sb2[HID], sw3[HID];
    __shared__ float sW2[HID*HID];

    const int t = threadIdx.x;
    if (t < HID) { sw1[t]=pw1[t]; sb1[t]=pb1[t]; sb2[t]=pb2[t]; sw3[t]=pw3[t]; }
    for (int i = t; i < HID*HID; i += 128) sW2[i] = pW2[i];
    __syncthreads();

    const int i = blockIdx.x * 128 + t;
    if (i > TBL) return;

    float zmin = ord2f(g_zmin_u), zmax = ord2f(g_zmax_u);
    float z = zmin + (zmax - zmin) * ((float)i / (float)TBL);

    // h2 accumulators in registers; h1 on the fly (no dynamic indexing)
    float h2[HID];
    #pragma unroll
    for (int kx = 0; kx < HID; kx++) h2[kx] = sb2[kx];

    #pragma unroll
    for (int j = 0; j < HID; j++) {
        float a  = fmaf(z, sw1[j], sb1[j]);
        float hj = fmaxf(a, 0.0f) + __logf(1.0f + __expf(-fabsf(a)));  // softplus
        #pragma unroll
        for (int kx = 0; kx < HID; kx++)
            h2[kx] = fmaf(hj, sW2[j*HID + kx], h2[kx]);
    }

    float acc = pb3[0];
    #pragma unroll
    for (int kx = 0; kx < HID; kx++)
        acc = fmaf(fmaxf(h2[kx], 0.0f), sw3[kx], acc);

    g_table[i] = acc;
}

// ---------------- K3: table lookup -> _xs + logp partials (x4) ----------
__global__ void __launch_bounds__(256) k_proj(
    const float* __restrict__ xs, const float* __restrict__ nstd,
    float* __restrict__ out)
{
    const int base = (blockIdx.x * 256 + threadIdx.x) * 4;

    float zmin = ord2f(g_zmin_u), zmax = ord2f(g_zmax_u);
    float inv_h = (float)TBL / (zmax - zmin);

    float4 zv = *(const float4*)(g_zs + base);
    float4 xv = *(const float4*)(xs + base);

    float std = nstd[0];
    float inv_std = 1.0f / std;
    float cterm = -logf(std) - 0.91893853320467274f;  // -log(std)-0.5*log(2pi)

    float zz[4] = {zv.x, zv.y, zv.z, zv.w};
    float xx[4] = {xv.x, xv.y, xv.z, xv.w};
    float oo[4];
    float lsum = 0.0f;

    #pragma unroll
    for (int k = 0; k < 4; k++) {
        float tt = (zz[k] - zmin) * inv_h;
        tt = fminf(fmaxf(tt, 0.0f), (float)TBL);
        int   j  = min((int)tt, TBL - 1);
        float fr = tt - (float)j;
        float v0 = g_table[j];
        float v1 = g_table[j+1];
        float xh = fmaf(v1 - v0, fr, v0);
        oo[k] = xh;
        float r = (xx[k] - xh) * inv_std;
        lsum += fmaf(-0.5f, r*r, cterm);
    }

    float2* p = (float2*)(out + 2 + base);   // 8B-aligned
    p[0] = make_float2(oo[0], oo[1]);
    p[1] = make_float2(oo[2], oo[3]);

    // deterministic block reduce
    float v = lsum;
    #pragma unroll
    for (int o = 16; o; o >>= 1) v += __shfl_xor_sync(0xffffffffu, v, o);
    __shared__ float sred[8];
    int w = threadIdx.x >> 5, l = threadIdx.x & 31;
    if (l == 0) sred[w] = v;
    __syncthreads();
    if (threadIdx.x == 0) {
        float s = 0.0f;
        #pragma unroll
        for (int k = 0; k < 8; k++) s += sred[k];
        g_part_logp[blockIdx.x] = s;
    }
}

// ---------------- K4: final deterministic reduction ----------------------
__global__ void __launch_bounds__(256) k_final(float* __restrict__ out)
{
    __shared__ double s[256];
    const int t = threadIdx.x;

    double a = 0.0;
    for (int i = t; i < K3_BLOCKS; i += 256) a += (double)g_part_logp[i];
    s[t] = a; __syncthreads();
    for (int o = 128; o; o >>= 1) { if (t < o) s[t] += s[t+o]; __syncthreads(); }
    double logp_sum = s[0];
    __syncthreads();

    s[t] = (t < K1_BLOCKS) ? (double)g_part_kl[t] : 0.0; __syncthreads();
    for (int o = 128; o; o >>= 1) { if (t < o) s[t] += s[t+o]; __syncthreads(); }
    double kl_sum = s[0];
    __syncthreads();

    s[t] = (t < K1_BLOCKS) ? (double)g_part_li[t] : 0.0; __syncthreads();
    for (int o = 128; o; o >>= 1) { if (t < o) s[t] += s[t+o]; __syncthreads(); }
    double li_sum = s[0];

    if (t == 0) {
        out[0] = (float)(logp_sum / (double)BB);
        out[1] = (float)((kl_sum + li_sum) / (double)BB);
    }
}

// ---------------- launch ----------------
extern "C" void kernel_launch(void* const* d_in, const int* in_sizes, int n_in,
                              void* d_out, int out_size)
{
    const float* xs    = (const float*)d_in[0];
    const float* ts    = (const float*)d_in[1];
    const float* nstd  = (const float*)d_in[2];
    const float* eps0  = (const float*)d_in[3];
    const float* bm    = (const float*)d_in[4];
    const float* ew1   = (const float*)d_in[5];
    const float* eb1   = (const float*)d_in[6];
    const float* ew2   = (const float*)d_in[7];
    const float* eb2   = (const float*)d_in[8];
    const float* qw    = (const float*)d_in[9];
    const float* qb    = (const float*)d_in[10];
    const float* fw1   = (const float*)d_in[11];
    const float* fb1   = (const float*)d_in[12];
    const float* fw2   = (const float*)d_in[13];
    const float* fb2   = (const float*)d_in[14];
    const float* pw1   = (const float*)d_in[15];
    const float* pb1   = (const float*)d_in[16];
    const float* pW2   = (const float*)d_in[17];
    const float* pb2   = (const float*)d_in[18];
    const float* pw3   = (const float*)d_in[19];
    const float* pb3   = (const float*)d_in[20];
    const float* pz0m  = (const float*)d_in[21];
    const float* pz0ls = (const float*)d_in[22];
    const float* kap   = (const float*)d_in[23];
    const float* the   = (const float*)d_in[24];
    const float* sig   = (const float*)d_in[25];

    float* out = (float*)d_out;

    k_init<<<1, 1>>>();
    k_scan<<<K1_BLOCKS, 128>>>(xs, ts, eps0, bm,
                               ew1, eb1, ew2, eb2, qw, qb,
                               fw1, fb1, fw2, fb2,
                               pz0m, pz0ls, kap, the, sig);
    k_table<<<(TBL + 1 + 127) / 128, 128>>>(pw1, pb1, pW2, pb2, pw3, pb3);
    k_proj<<<K3_BLOCKS, 256>>>(xs, nstd, out);
    k_final<<<1, 256>>>(out);
}

// round 5
// speedup vs baseline: 3.2791x; 1.7969x over previous
#include <cuda_runtime.h>
#include <math.h>

#define NT   45
#define BB   32768
#define HID  64
#define TBL  16384
#define K1_BLOCKS (BB/128)            // 256
#define KE_BLOCKS ((NT*BB)/256)       // 5760
#define K3_BLOCKS ((NT*BB)/(256*8))   // 720

// ---------------- device scratch (static, no allocation) ----------------
__device__ float    g_zs[NT*BB];          // 5.9 MB latent path
__device__ float2   g_ctx[NT*BB];         // 11.8 MB encoder output (c0,c1)
__device__ float    g_table[TBL+1];       // P(z) lookup table
__device__ unsigned g_zmin_u, g_zmax_u;   // ordered-uint encoded range
__device__ float    g_part_li[K1_BLOCKS];
__device__ float    g_part_kl[K1_BLOCKS];
__device__ float    g_part_logp[K3_BLOCKS];

// monotone float <-> uint mapping for atomicMin/Max on floats
__device__ __forceinline__ unsigned f2ord(float f) {
    unsigned u = __float_as_uint(f);
    return (u & 0x80000000u) ? ~u : (u | 0x80000000u);
}
__device__ __forceinline__ float ord2f(unsigned u) {
    u = (u & 0x80000000u) ? (u ^ 0x80000000u) : ~u;
    return __uint_as_float(u);
}

// ---------------- K0: reset per-launch state (graph replays!) -----------
__global__ void k_init() {
    g_zmin_u = 0xFFFFFFFFu;
    g_zmax_u = 0u;
}

// ---------------- Ke: encoder for ALL (n,b) — bit-identical op sequence -
// ctx(x) has no dependence on z, so it is hoisted out of the sequential
// scan into a fully-parallel kernel. fp32 values round-trip exactly via
// g_ctx, so the scan consumes byte-identical cc0/cc1 vs the R4 kernel.
__global__ void __launch_bounds__(256) k_enc(
    const float* __restrict__ xs,
    const float* __restrict__ ew1, const float* __restrict__ eb1,
    const float* __restrict__ ew2, const float* __restrict__ eb2)
{
    __shared__ float4 sE[HID];   // {enc_w1, enc_b1, enc_w2[:,0], enc_w2[:,1]}
    const int t = threadIdx.x;
    if (t < HID)
        sE[t] = make_float4(ew1[t], eb1[t], ew2[2*t], ew2[2*t+1]);
    __syncthreads();

    const int idx = blockIdx.x * 256 + t;
    const float x = xs[idx];
    float c0 = eb2[0], c1 = eb2[1];
    #pragma unroll
    for (int j = 0; j < HID; j++) {
        float4 e = sE[j];
        float h = fmaxf(fmaf(x, e.x, e.y), 0.0f);
        c0 = fmaf(h, e.z, c0);
        c1 = fmaf(h, e.w, c1);
    }
    g_ctx[idx] = make_float2(c0, c1);
}

// ---------------- K1: posterior + SDE scan (drift only in the loop) -----
// Numerics bit-identical to the R4 kernel that passed at rel_err 1.04e-5.
__global__ void __launch_bounds__(128) k_scan(
    const float* __restrict__ ts,
    const float* __restrict__ eps0,const float* __restrict__ bm,
    const float* __restrict__ qw,  const float* __restrict__ qb,
    const float* __restrict__ fw1, const float* __restrict__ fb1,
    const float* __restrict__ fw2, const float* __restrict__ fb2,
    const float* __restrict__ pz0m,const float* __restrict__ pz0ls,
    const float* __restrict__ kap, const float* __restrict__ the,
    const float* __restrict__ sig)
{
    __shared__ float4 sF[HID];    // {f_w1[0], f_w1[1], f_w1[2], f_b1}
    __shared__ float  sW2[HID];   // f_w2
    __shared__ float  sTs[NT];
    __shared__ float  sred[4];

    const int t = threadIdx.x;
    if (t < HID) {
        sF[t]  = make_float4(fw1[t], fw1[HID+t], fw1[2*HID+t], fb1[t]);
        sW2[t] = fw2[t];
    }
    if (t < NT) sTs[t] = ts[t];
    __syncthreads();

    const int b = blockIdx.x * 128 + t;

    const float fb2_s = fb2[0];
    const float kappa = kap[0], theta = the[0], sigma = sig[0];
    const float inv_sig = 1.0f / sigma;
    const float pm = pz0m[0], pls = pz0ls[0];

    // posterior from precomputed ctx[0]
    float2 c = g_ctx[b];
    float qm  = fmaf(c.x, qw[0], fmaf(c.y, qw[2], qb[0]));
    float qls = fmaf(c.x, qw[1], fmaf(c.y, qw[3], qb[1]));

    float z = qm + expf(qls) * eps0[b];

    float dqm = qm - pm;
    float kl  = pls - qls
              + (expf(2.0f*qls) + dqm*dqm) / (2.0f * expf(2.0f*pls))
              - 0.5f;

    g_zs[b] = z;
    float zmn = z, zmx = z;
    float li = 0.0f;

    float2 cn  = g_ctx[BB + b];   // prefetch next-step ctx / bm
    float  bmv = bm[b];

    #pragma unroll 1
    for (int n = 1; n < NT; n++) {
        const float cc0 = cn.x, cc1 = cn.y, dwe = bmv;
        if (n + 1 < NT) { cn = g_ctx[(n+1)*BB + b]; bmv = bm[n*BB + b]; }
        const float dt = sTs[n] - sTs[n-1];

        // drift f([z, c0, c1])  (identical op sequence to R4)
        float f = fb2_s;
        #pragma unroll
        for (int j = 0; j < HID; j++) {
            float4 w = sF[j];
            float h = fmaf(z, w.x, fmaf(cc0, w.y, fmaf(cc1, w.z, w.w)));
            h = fmaxf(h, 0.0f);
            f = fmaf(h, sW2[j], f);
        }

        float u = (f - kappa * (theta - z)) * inv_sig;
        li = fmaf(0.5f * u * u, dt, li);

        float dw = dwe * sqrtf(dt);
        z = fmaf(f, dt, fmaf(sigma, dw, z));

        g_zs[n*BB + b] = z;
        zmn = fminf(zmn, z);
        zmx = fmaxf(zmx, z);
    }

    // range: order-invariant -> atomics fine
    #pragma unroll
    for (int o = 16; o; o >>= 1) {
        zmn = fminf(zmn, __shfl_xor_sync(0xffffffffu, zmn, o));
        zmx = fmaxf(zmx, __shfl_xor_sync(0xffffffffu, zmx, o));
    }
    if ((t & 31) == 0) {
        atomicMin(&g_zmin_u, f2ord(zmn));
        atomicMax(&g_zmax_u, f2ord(zmx));
    }

    // deterministic fixed-order reductions
    float vli = li, vkl = kl;
    #pragma unroll
    for (int o = 16; o; o >>= 1) {
        vli += __shfl_xor_sync(0xffffffffu, vli, o);
        vkl += __shfl_xor_sync(0xffffffffu, vkl, o);
    }
    int w = t >> 5, l = t & 31;
    if (l == 0) sred[w] = vli;
    __syncthreads();
    if (t == 0) g_part_li[blockIdx.x] = (sred[0]+sred[1])+(sred[2]+sred[3]);
    __syncthreads();
    if (l == 0) sred[w] = vkl;
    __syncthreads();
    if (t == 0) g_part_kl[blockIdx.x] = (sred[0]+sred[1])+(sred[2]+sred[3]);
}

// ---------------- K2: tabulate P(z) (full unroll, registers only) -------
__global__ void __launch_bounds__(128) k_table(
    const float* __restrict__ pw1, const float* __restrict__ pb1,
    const float* __restrict__ pW2, const float* __restrict__ pb2,
    const float* __restrict__ pw3, const float* __restrict__ pb3)
{
    __shared__ float sw1[HID], sb1[HID], sb2[HID], sw3[HID];
    __shared__ float sW2[HID*HID];

    const int t = threadIdx.x;
    if (t < HID) { sw1[t]=pw1[t]; sb1[t]=pb1[t]; sb2[t]=pb2[t]; sw3[t]=pw3[t]; }
    for (int i = t; i < HID*HID; i += 128) sW2[i] = pW2[i];
    __syncthreads();

    const int i = blockIdx.x * 128 + t;
    if (i > TBL) return;

    float zmin = ord2f(g_zmin_u), zmax = ord2f(g_zmax_u);
    float z = zmin + (zmax - zmin) * ((float)i / (float)TBL);

    float h2[HID];
    #pragma unroll
    for (int kx = 0; kx < HID; kx++) h2[kx] = sb2[kx];

    #pragma unroll
    for (int j = 0; j < HID; j++) {
        float a  = fmaf(z, sw1[j], sb1[j]);
        float hj = fmaxf(a, 0.0f) + __logf(1.0f + __expf(-fabsf(a)));  // softplus
        #pragma unroll
        for (int kx = 0; kx < HID; kx++)
            h2[kx] = fmaf(hj, sW2[j*HID + kx], h2[kx]);
    }

    float acc = pb3[0];
    #pragma unroll
    for (int kx = 0; kx < HID; kx++)
        acc = fmaf(fmaxf(h2[kx], 0.0f), sw3[kx], acc);

    g_table[i] = acc;
}

// ---------------- K3: table lookup -> _xs + logp partials (x8) ----------
__global__ void __launch_bounds__(256) k_proj(
    const float* __restrict__ xs, const float* __restrict__ nstd,
    float* __restrict__ out)
{
    const int base = (blockIdx.x * 256 + threadIdx.x) * 8;

    float zmin = ord2f(g_zmin_u), zmax = ord2f(g_zmax_u);
    float inv_h = (float)TBL / (zmax - zmin);

    float4 zv0 = *(const float4*)(g_zs + base);
    float4 zv1 = *(const float4*)(g_zs + base + 4);
    float4 xv0 = *(const float4*)(xs + base);
    float4 xv1 = *(const float4*)(xs + base + 4);

    float std = nstd[0];
    float inv_std = 1.0f / std;
    float cterm = -logf(std) - 0.91893853320467274f;  // -log(std)-0.5*log(2pi)

    float zz[8] = {zv0.x, zv0.y, zv0.z, zv0.w, zv1.x, zv1.y, zv1.z, zv1.w};
    float xx[8] = {xv0.x, xv0.y, xv0.z, xv0.w, xv1.x, xv1.y, xv1.z, xv1.w};
    float oo[8];
    float lsum = 0.0f;

    #pragma unroll
    for (int k = 0; k < 8; k++) {
        float tt = (zz[k] - zmin) * inv_h;
        tt = fminf(fmaxf(tt, 0.0f), (float)TBL);
        int   j  = min((int)tt, TBL - 1);
        float fr = tt - (float)j;
        float v0 = g_table[j];
        float v1 = g_table[j+1];
        float xh = fmaf(v1 - v0, fr, v0);
        oo[k] = xh;
        float r = (xx[k] - xh) * inv_std;
        lsum += fmaf(-0.5f, r*r, cterm);
    }

    float2* p = (float2*)(out + 2 + base);   // 8B-aligned
    #pragma unroll
    for (int k = 0; k < 4; k++)
        p[k] = make_float2(oo[2*k], oo[2*k+1]);

    // deterministic block reduce
    float v = lsum;
    #pragma unroll
    for (int o = 16; o; o >>= 1) v += __shfl_xor_sync(0xffffffffu, v, o);
    __shared__ float sred[8];
    int w = threadIdx.x >> 5, l = threadIdx.x & 31;
    if (l == 0) sred[w] = v;
    __syncthreads();
    if (threadIdx.x == 0) {
        float s = 0.0f;
        #pragma unroll
        for (int k = 0; k < 8; k++) s += sred[k];
        g_part_logp[blockIdx.x] = s;
    }
}

// ---------------- K4: final deterministic reduction ----------------------
__global__ void __launch_bounds__(256) k_final(float* __restrict__ out)
{
    __shared__ double s[256];
    const int t = threadIdx.x;

    double a = 0.0;
    for (int i = t; i < K3_BLOCKS; i += 256) a += (double)g_part_logp[i];
    s[t] = a; __syncthreads();
    for (int o = 128; o; o >>= 1) { if (t < o) s[t] += s[t+o]; __syncthreads(); }
    double logp_sum = s[0];
    __syncthreads();

    s[t] = (t < K1_BLOCKS) ? (double)g_part_kl[t] : 0.0; __syncthreads();
    for (int o = 128; o; o >>= 1) { if (t < o) s[t] += s[t+o]; __syncthreads(); }
    double kl_sum = s[0];
    __syncthreads();

    s[t] = (t < K1_BLOCKS) ? (double)g_part_li[t] : 0.0; __syncthreads();
    for (int o = 128; o; o >>= 1) { if (t < o) s[t] += s[t+o]; __syncthreads(); }
    double li_sum = s[0];

    if (t == 0) {
        out[0] = (float)(logp_sum / (double)BB);
        out[1] = (float)((kl_sum + li_sum) / (double)BB);
    }
}

// ---------------- launch ----------------
extern "C" void kernel_launch(void* const* d_in, const int* in_sizes, int n_in,
                              void* d_out, int out_size)
{
    const float* xs    = (const float*)d_in[0];
    const float* ts    = (const float*)d_in[1];
    const float* nstd  = (const float*)d_in[2];
    const float* eps0  = (const float*)d_in[3];
    const float* bm    = (const float*)d_in[4];
    const float* ew1   = (const float*)d_in[5];
    const float* eb1   = (const float*)d_in[6];
    const float* ew2   = (const float*)d_in[7];
    const float* eb2   = (const float*)d_in[8];
    const float* qw    = (const float*)d_in[9];
    const float* qb    = (const float*)d_in[10];
    const float* fw1   = (const float*)d_in[11];
    const float* fb1   = (const float*)d_in[12];
    const float* fw2   = (const float*)d_in[13];
    const float* fb2   = (const float*)d_in[14];
    const float* pw1   = (const float*)d_in[15];
    const float* pb1   = (const float*)d_in[16];
    const float* pW2   = (const float*)d_in[17];
    const float* pb2   = (const float*)d_in[18];
    const float* pw3   = (const float*)d_in[19];
    const float* pb3   = (const float*)d_in[20];
    const float* pz0m  = (const float*)d_in[21];
    const float* pz0ls = (const float*)d_in[22];
    const float* kap   = (const float*)d_in[23];
    const float* the   = (const float*)d_in[24];
    const float* sig   = (const float*)d_in[25];

    float* out = (float*)d_out;

    k_init<<<1, 1>>>();
    k_enc<<<KE_BLOCKS, 256>>>(xs, ew1, eb1, ew2, eb2);
    k_scan<<<K1_BLOCKS, 128>>>(ts, eps0, bm, qw, qb,
                               fw1, fb1, fw2, fb2,
                               pz0m, pz0ls, kap, the, sig);
    k_table<<<(TBL + 1 + 127) / 128, 128>>>(pw1, pb1, pW2, pb2, pw3, pb3);
    k_proj<<<K3_BLOCKS, 256>>>(xs, nstd, out);
    k_final<<<1, 256>>>(out);
}

// round 6
// speedup vs baseline: 3.7532x; 1.1446x over previous
#include <cuda_runtime.h>
#include <math.h>

#define NT   45
#define BB   32768
#define HID  64
#define TBL  4096
#define ZPB  16
#define K1_BLOCKS (BB/128)             // 256
#define KE_BLOCKS ((NT*BB)/(256*2))    // 2880
#define K3_BLOCKS ((NT*BB)/(256*8))    // 720
#define TBL_BLOCKS ((TBL + ZPB) / ZPB) // 257

typedef unsigned long long ull;

// ---------------- device scratch (static, no allocation) ----------------
__device__ float    g_zs[NT*BB];          // latent path
__device__ float2   g_ctx[NT*BB];         // encoder output (c0,c1)
__device__ float    g_table[TBL+1];       // P(z) lookup table
__device__ unsigned g_zmin_u = 0xFFFFFFFFu;   // reset by k_final each launch
__device__ unsigned g_zmax_u = 0u;
__device__ float    g_part_li[K1_BLOCKS];
__device__ float    g_part_kl[K1_BLOCKS];
__device__ float    g_part_logp[K3_BLOCKS];

// monotone float <-> uint mapping for atomicMin/Max on floats
__device__ __forceinline__ unsigned f2ord(float f) {
    unsigned u = __float_as_uint(f);
    return (u & 0x80000000u) ? ~u : (u | 0x80000000u);
}
__device__ __forceinline__ float ord2f(unsigned u) {
    u = (u & 0x80000000u) ? (u ^ 0x80000000u) : ~u;
    return __uint_as_float(u);
}

// ---------------- packed fp32x2 helpers (per-lane IEEE fp32, bit-exact) --
__device__ __forceinline__ ull pack2(float lo, float hi) {
    ull r;
    asm("mov.b64 %0, {%1, %2};" : "=l"(r) : "f"(lo), "f"(hi));
    return r;
}
__device__ __forceinline__ void unpack2(ull v, float& lo, float& hi) {
    asm("mov.b64 {%0, %1}, %2;" : "=f"(lo), "=f"(hi) : "l"(v));
}
__device__ __forceinline__ ull fma2(ull a, ull b, ull c) {
    ull d;
    asm("fma.rn.f32x2 %0, %1, %2, %3;" : "=l"(d) : "l"(a), "l"(b), "l"(c));
    return d;
}

// ---------------- Ke: encoder, 2 batch elements per thread, f32x2 -------
// Per-element op sequence identical to the validated scalar version
// (lanes of the packed ops are independent IEEE fp32).
__global__ void __launch_bounds__(256) k_enc(
    const float* __restrict__ xs,
    const float* __restrict__ ew1, const float* __restrict__ eb1,
    const float* __restrict__ ew2, const float* __restrict__ eb2)
{
    __shared__ ulonglong2 sE1[HID];   // {w1 splat, b1 splat}
    __shared__ ulonglong2 sE2[HID];   // {w2[:,0] splat, w2[:,1] splat}

    const int t = threadIdx.x;
    if (t < HID) {
        float w1 = ew1[t], b1 = eb1[t], u0 = ew2[2*t], u1 = ew2[2*t+1];
        ulonglong2 e1, e2;
        e1.x = pack2(w1, w1); e1.y = pack2(b1, b1);
        e2.x = pack2(u0, u0); e2.y = pack2(u1, u1);
        sE1[t] = e1; sE2[t] = e2;
    }
    __syncthreads();

    const int idx = (blockIdx.x * 256 + t) * 2;
    float2 xv = *(const float2*)(xs + idx);
    ull xp = pack2(xv.x, xv.y);

    float eb0 = eb2[0], eb1v = eb2[1];
    ull c0p = pack2(eb0, eb0);
    ull c1p = pack2(eb1v, eb1v);

    #pragma unroll
    for (int j = 0; j < HID; j++) {
        ulonglong2 E1 = sE1[j], E2 = sE2[j];
        ull h = fma2(xp, E1.x, E1.y);
        float h0, h1; unpack2(h, h0, h1);
        h = pack2(fmaxf(h0, 0.0f), fmaxf(h1, 0.0f));
        c0p = fma2(h, E2.x, c0p);
        c1p = fma2(h, E2.y, c1p);
    }

    float c0a, c0b, c1a, c1b;
    unpack2(c0p, c0a, c0b);
    unpack2(c1p, c1a, c1b);
    *(float4*)(g_ctx + idx) = make_float4(c0a, c1a, c0b, c1b);
}

// ---------------- K1: posterior + SDE scan, drift rows packed f32x2 -----
// Per-row h chain and the scalar in-order f accumulation are bit-identical
// to the R4/R5 kernel that passed at rel_err 1.04e-5.
__global__ void __launch_bounds__(128) k_scan(
    const float* __restrict__ ts,
    const float* __restrict__ eps0,const float* __restrict__ bm,
    const float* __restrict__ qw,  const float* __restrict__ qb,
    const float* __restrict__ fw1, const float* __restrict__ fb1,
    const float* __restrict__ fw2, const float* __restrict__ fb2,
    const float* __restrict__ pz0m,const float* __restrict__ pz0ls,
    const float* __restrict__ kap, const float* __restrict__ the,
    const float* __restrict__ sig)
{
    __shared__ ulonglong2 sWA[32];   // {wx pair, wy pair}
    __shared__ ulonglong2 sWB[32];   // {wz pair, wb pair}
    __shared__ float2     sW22[32];  // f_w2 pairs
    __shared__ float      sTs[NT];
    __shared__ float      sred[4];

    const int t = threadIdx.x;
    if (t < 32) {
        int p = t;
        ulonglong2 A, B;
        A.x = pack2(fw1[2*p],       fw1[2*p+1]);        // w_z
        A.y = pack2(fw1[HID+2*p],   fw1[HID+2*p+1]);    // w_c0
        B.x = pack2(fw1[2*HID+2*p], fw1[2*HID+2*p+1]);  // w_c1
        B.y = pack2(fb1[2*p],       fb1[2*p+1]);        // bias
        sWA[p] = A; sWB[p] = B;
        sW22[p] = make_float2(fw2[2*p], fw2[2*p+1]);
    }
    if (t < NT) sTs[t] = ts[t];
    __syncthreads();

    const int b = blockIdx.x * 128 + t;

    const float fb2_s = fb2[0];
    const float kappa = kap[0], theta = the[0], sigma = sig[0];
    const float inv_sig = 1.0f / sigma;
    const float pm = pz0m[0], pls = pz0ls[0];

    // posterior from precomputed ctx[0]
    float2 c = g_ctx[b];
    float qm  = fmaf(c.x, qw[0], fmaf(c.y, qw[2], qb[0]));
    float qls = fmaf(c.x, qw[1], fmaf(c.y, qw[3], qb[1]));

    float z = qm + expf(qls) * eps0[b];

    float dqm = qm - pm;
    float kl  = pls - qls
              + (expf(2.0f*qls) + dqm*dqm) / (2.0f * expf(2.0f*pls))
              - 0.5f;

    g_zs[b] = z;
    float zmn = z, zmx = z;
    float li = 0.0f;

    float2 cn  = g_ctx[BB + b];   // prefetch next-step ctx / bm
    float  bmv = bm[b];

    #pragma unroll 1
    for (int n = 1; n < NT; n++) {
        const float cc0 = cn.x, cc1 = cn.y, dwe = bmv;
        if (n + 1 < NT) { cn = g_ctx[(n+1)*BB + b]; bmv = bm[n*BB + b]; }
        const float dt = sTs[n] - sTs[n-1];

        const ull zp  = pack2(z,   z);
        const ull c0p = pack2(cc0, cc0);
        const ull c1p = pack2(cc1, cc1);

        // drift f([z, c0, c1]) — rows paired, per-row math identical:
        // h = fma(z, wx, fma(cc0, wy, fma(cc1, wz, wb)))
        float f = fb2_s;
        #pragma unroll
        for (int p = 0; p < 32; p++) {
            ulonglong2 A = sWA[p], B = sWB[p];
            ull d = fma2(c1p, B.x, B.y);
            d = fma2(c0p, A.y, d);
            d = fma2(zp,  A.x, d);
            float h0, h1; unpack2(d, h0, h1);
            float2 w2 = sW22[p];
            f = fmaf(fmaxf(h0, 0.0f), w2.x, f);
            f = fmaf(fmaxf(h1, 0.0f), w2.y, f);
        }

        float u = (f - kappa * (theta - z)) * inv_sig;
        li = fmaf(0.5f * u * u, dt, li);

        float dw = dwe * sqrtf(dt);
        z = fmaf(f, dt, fmaf(sigma, dw, z));

        g_zs[n*BB + b] = z;
        zmn = fminf(zmn, z);
        zmx = fmaxf(zmx, z);
    }

    // range: order-invariant -> atomics fine
    #pragma unroll
    for (int o = 16; o; o >>= 1) {
        zmn = fminf(zmn, __shfl_xor_sync(0xffffffffu, zmn, o));
        zmx = fmaxf(zmx, __shfl_xor_sync(0xffffffffu, zmx, o));
    }
    if ((t & 31) == 0) {
        atomicMin(&g_zmin_u, f2ord(zmn));
        atomicMax(&g_zmax_u, f2ord(zmx));
    }

    // deterministic fixed-order reductions
    float vli = li, vkl = kl;
    #pragma unroll
    for (int o = 16; o; o >>= 1) {
        vli += __shfl_xor_sync(0xffffffffu, vli, o);
        vkl += __shfl_xor_sync(0xffffffffu, vkl, o);
    }
    int w = t >> 5, l = t & 31;
    if (l == 0) sred[w] = vli;
    __syncthreads();
    if (t == 0) g_part_li[blockIdx.x] = (sred[0]+sred[1])+(sred[2]+sred[3]);
    __syncthreads();
    if (l == 0) sred[w] = vkl;
    __syncthreads();
    if (t == 0) g_part_kl[blockIdx.x] = (sred[0]+sred[1])+(sred[2]+sred[3]);
}

// ---------------- K2: tabulate P(z), 4 lanes cooperate per z-point ------
__global__ void __launch_bounds__(64) k_table(
    const float* __restrict__ pw1, const float* __restrict__ pb1,
    const float* __restrict__ pW2, const float* __restrict__ pb2,
    const float* __restrict__ pw3, const float* __restrict__ pb3)
{
    __shared__ float sw1[HID], sb1[HID], sb2[HID], sw3[HID];
    __shared__ float sW2[HID*HID];
    __shared__ float h1s[ZPB][HID+4];   // +4 pad: conflict-free column reads

    const int t = threadIdx.x;   // 64 threads
    { sw1[t]=pw1[t]; sb1[t]=pb1[t]; sb2[t]=pb2[t]; sw3[t]=pw3[t]; }
    for (int i = t; i < HID*HID; i += 64) sW2[i] = pW2[i];
    __syncthreads();

    const int zi    = t >> 2;     // 0..15: z-point within block
    const int lane4 = t & 3;      // 0..3 : 16-column slice
    const int gz    = blockIdx.x * ZPB + zi;

    float zmin = ord2f(g_zmin_u), zmax = ord2f(g_zmax_u);
    float z = zmin + (zmax - zmin) * ((float)gz / (float)TBL);

    // phase 1: each lane computes 16 softplus values of h1
    #pragma unroll
    for (int jj = 0; jj < 16; jj++) {
        int j = lane4 * 16 + jj;
        float a = fmaf(z, sw1[j], sb1[j]);
        h1s[zi][j] = fmaxf(a, 0.0f) + __logf(1.0f + __expf(-fabsf(a)));
    }
    __syncthreads();

    // phase 2: each lane accumulates its 16 h2 columns over all 64 j
    const int c0 = lane4 * 16;
    float h2[16];
    #pragma unroll
    for (int k = 0; k < 16; k++) h2[k] = sb2[c0 + k];

    #pragma unroll 8
    for (int j = 0; j < HID; j++) {
        float hj = h1s[zi][j];
        #pragma unroll
        for (int k = 0; k < 16; k++)
            h2[k] = fmaf(hj, sW2[j*HID + c0 + k], h2[k]);
    }

    float acc = 0.0f;
    #pragma unroll
    for (int k = 0; k < 16; k++)
        acc = fmaf(fmaxf(h2[k], 0.0f), sw3[c0 + k], acc);

    // combine the 4 column slices
    acc += __shfl_xor_sync(0xffffffffu, acc, 1);
    acc += __shfl_xor_sync(0xffffffffu, acc, 2);
    if (lane4 == 0 && gz <= TBL) g_table[gz] = acc + pb3[0];
}

// ---------------- K3: table lookup -> _xs + logp partials (x8) ----------
__global__ void __launch_bounds__(256) k_proj(
    const float* __restrict__ xs, const float* __restrict__ nstd,
    float* __restrict__ out)
{
    const int base = (blockIdx.x * 256 + threadIdx.x) * 8;

    float zmin = ord2f(g_zmin_u), zmax = ord2f(g_zmax_u);
    float inv_h = (float)TBL / (zmax - zmin);

    float4 zv0 = *(const float4*)(g_zs + base);
    float4 zv1 = *(const float4*)(g_zs + base + 4);
    float4 xv0 = *(const float4*)(xs + base);
    float4 xv1 = *(const float4*)(xs + base + 4);

    float std = nstd[0];
    float inv_std = 1.0f / std;
    float cterm = -logf(std) - 0.91893853320467274f;  // -log(std)-0.5*log(2pi)

    float zz[8] = {zv0.x, zv0.y, zv0.z, zv0.w, zv1.x, zv1.y, zv1.z, zv1.w};
    float xx[8] = {xv0.x, xv0.y, xv0.z, xv0.w, xv1.x, xv1.y, xv1.z, xv1.w};
    float oo[8];
    float lsum = 0.0f;

    #pragma unroll
    for (int k = 0; k < 8; k++) {
        float tt = (zz[k] - zmin) * inv_h;
        tt = fminf(fmaxf(tt, 0.0f), (float)TBL);
        int   j  = min((int)tt, TBL - 1);
        float fr = tt - (float)j;
        float v0 = g_table[j];
        float v1 = g_table[j+1];
        float xh = fmaf(v1 - v0, fr, v0);
        oo[k] = xh;
        float r = (xx[k] - xh) * inv_std;
        lsum += fmaf(-0.5f, r*r, cterm);
    }

    float2* p = (float2*)(out + 2 + base);   // 8B-aligned
    #pragma unroll
    for (int k = 0; k < 4; k++)
        p[k] = make_float2(oo[2*k], oo[2*k+1]);

    // deterministic block reduce
    float v = lsum;
    #pragma unroll
    for (int o = 16; o; o >>= 1) v += __shfl_xor_sync(0xffffffffu, v, o);
    __shared__ float sred[8];
    int w = threadIdx.x >> 5, l = threadIdx.x & 31;
    if (l == 0) sred[w] = v;
    __syncthreads();
    if (threadIdx.x == 0) {
        float s = 0.0f;
        #pragma unroll
        for (int k = 0; k < 8; k++) s += sred[k];
        g_part_logp[blockIdx.x] = s;
    }
}

// ---------------- K4: final reduction + state reset for next launch -----
__global__ void __launch_bounds__(256) k_final(float* __restrict__ out)
{
    __shared__ double s[256];
    const int t = threadIdx.x;

    double a = 0.0;
    for (int i = t; i < K3_BLOCKS; i += 256) a += (double)g_part_logp[i];
    s[t] = a; __syncthreads();
    for (int o = 128; o; o >>= 1) { if (t < o) s[t] += s[t+o]; __syncthreads(); }
    double logp_sum = s[0];
    __syncthreads();

    s[t] = (t < K1_BLOCKS) ? (double)g_part_kl[t] : 0.0; __syncthreads();
    for (int o = 128; o; o >>= 1) { if (t < o) s[t] += s[t+o]; __syncthreads(); }
    double kl_sum = s[0];
    __syncthreads();

    s[t] = (t < K1_BLOCKS) ? (double)g_part_li[t] : 0.0; __syncthreads();
    for (int o = 128; o; o >>= 1) { if (t < o) s[t] += s[t+o]; __syncthreads(); }
    double li_sum = s[0];

    if (t == 0) {
        out[0] = (float)(logp_sum / (double)BB);
        out[1] = (float)((kl_sum + li_sum) / (double)BB);
        // reset min/max state for the next (replayed) launch
        g_zmin_u = 0xFFFFFFFFu;
        g_zmax_u = 0u;
    }
}

// ---------------- launch ----------------
extern "C" void kernel_launch(void* const* d_in, const int* in_sizes, int n_in,
                              void* d_out, int out_size)
{
    const float* xs    = (const float*)d_in[0];
    const float* ts    = (const float*)d_in[1];
    const float* nstd  = (const float*)d_in[2];
    const float* eps0  = (const float*)d_in[3];
    const float* bm    = (const float*)d_in[4];
    const float* ew1   = (const float*)d_in[5];
    const float* eb1   = (const float*)d_in[6];
    const float* ew2   = (const float*)d_in[7];
    const float* eb2   = (const float*)d_in[8];
    const float* qw    = (const float*)d_in[9];
    const float* qb    = (const float*)d_in[10];
    const float* fw1   = (const float*)d_in[11];
    const float* fb1   = (const float*)d_in[12];
    const float* fw2   = (const float*)d_in[13];
    const float* fb2   = (const float*)d_in[14];
    const float* pw1   = (const float*)d_in[15];
    const float* pb1   = (const float*)d_in[16];
    const float* pW2   = (const float*)d_in[17];
    const float* pb2   = (const float*)d_in[18];
    const float* pw3   = (const float*)d_in[19];
    const float* pb3   = (const float*)d_in[20];
    const float* pz0m  = (const float*)d_in[21];
    const float* pz0ls = (const float*)d_in[22];
    const float* kap   = (const float*)d_in[23];
    const float* the   = (const float*)d_in[24];
    const float* sig   = (const float*)d_in[25];

    float* out = (float*)d_out;

    k_enc<<<KE_BLOCKS, 256>>>(xs, ew1, eb1, ew2, eb2);
    k_scan<<<K1_BLOCKS, 128>>>(ts, eps0, bm, qw, qb,
                               fw1, fb1, fw2, fb2,
                               pz0m, pz0ls, kap, the, sig);
    k_table<<<TBL_BLOCKS, 64>>>(pw1, pb1, pW2, pb2, pw3, pb3);
    k_proj<<<K3_BLOCKS, 256>>>(xs, nstd, out);
    k_final<<<1, 256>>>(out);
}

// round 7
// speedup vs baseline: 3.8653x; 1.0299x over previous
#include <cuda_runtime.h>
#include <math.h>

#define NT   45
#define BB   32768
#define HID  64
#define TBL  4096
#define ZPB  16
#define K1_BLOCKS (BB/128)             // 256
#define KE_TOTAL  ((NT*BB)/(256*4))    // 1440 enc blocks total (4 elems/thread)
#define KE_SPLIT  (KE_TOTAL/3)         // 480 per launch
#define K3_BLOCKS ((NT*BB)/(256*8))    // 720
#define TBL_BLOCKS ((TBL + ZPB) / ZPB) // 257

typedef unsigned long long ull;

// ---------------- device scratch (static, no allocation) ----------------
__device__ float    g_zs[NT*BB];          // latent path
__device__ float2   g_ctx[NT*BB];         // encoder output (c0,c1)
__device__ float    g_table[TBL+1];       // P(z) lookup table
__device__ unsigned g_zmin_u = 0xFFFFFFFFu;
__device__ unsigned g_zmax_u = 0u;
__device__ unsigned g_done   = 0u;        // last-block flag (self-resetting)
__device__ float    g_part_li[K1_BLOCKS];
__device__ float    g_part_kl[K1_BLOCKS];
__device__ float    g_part_logp[K3_BLOCKS];

// monotone float <-> uint mapping for atomicMin/Max on floats
__device__ __forceinline__ unsigned f2ord(float f) {
    unsigned u = __float_as_uint(f);
    return (u & 0x80000000u) ? ~u : (u | 0x80000000u);
}
__device__ __forceinline__ float ord2f(unsigned u) {
    u = (u & 0x80000000u) ? (u ^ 0x80000000u) : ~u;
    return __uint_as_float(u);
}

// ---------------- packed fp32x2 helpers (per-lane IEEE fp32, bit-exact) --
__device__ __forceinline__ ull pack2(float lo, float hi) {
    ull r;
    asm("mov.b64 %0, {%1, %2};" : "=l"(r) : "f"(lo), "f"(hi));
    return r;
}
__device__ __forceinline__ void unpack2(ull v, float& lo, float& hi) {
    asm("mov.b64 {%0, %1}, %2;" : "=f"(lo), "=f"(hi) : "l"(v));
}
__device__ __forceinline__ ull fma2(ull a, ull b, ull c) {
    ull d;
    asm("fma.rn.f32x2 %0, %1, %2, %3;" : "=l"(d) : "l"(a), "l"(b), "l"(c));
    return d;
}

// ---------------- Ke: encoder, 4 batch elements per thread, f32x2 -------
// Per-element op sequence identical to the validated version (independent
// IEEE fp32 lanes). Launched 3x over disjoint block ranges so k_scan is
// the 4th launch (profiler slot).
__global__ void __launch_bounds__(256) k_enc(
    const float* __restrict__ xs,
    const float* __restrict__ ew1, const float* __restrict__ eb1,
    const float* __restrict__ ew2, const float* __restrict__ eb2,
    int block_base)
{
    __shared__ ulonglong2 sE1[HID];   // {w1 splat, b1 splat}
    __shared__ ulonglong2 sE2[HID];   // {w2[:,0] splat, w2[:,1] splat}

    const int t = threadIdx.x;
    if (t < HID) {
        float w1 = ew1[t], b1 = eb1[t], u0 = ew2[2*t], u1 = ew2[2*t+1];
        ulonglong2 e1, e2;
        e1.x = pack2(w1, w1); e1.y = pack2(b1, b1);
        e2.x = pack2(u0, u0); e2.y = pack2(u1, u1);
        sE1[t] = e1; sE2[t] = e2;
    }
    // reset min/max state for this launch (first enc launch, one thread)
    if (block_base == 0 && blockIdx.x == 0 && t == 0) {
        g_zmin_u = 0xFFFFFFFFu;
        g_zmax_u = 0u;
    }
    __syncthreads();

    const int idx = ((block_base + blockIdx.x) * 256 + t) * 4;
    float4 xv = *(const float4*)(xs + idx);
    ull xa = pack2(xv.x, xv.y);
    ull xb = pack2(xv.z, xv.w);

    float eb0 = eb2[0], eb1v = eb2[1];
    ull c0a = pack2(eb0, eb0),  c0b = c0a;
    ull c1a = pack2(eb1v, eb1v), c1b = c1a;

    #pragma unroll
    for (int j = 0; j < HID; j++) {
        ulonglong2 E1 = sE1[j], E2 = sE2[j];
        ull ha = fma2(xa, E1.x, E1.y);
        ull hb = fma2(xb, E1.x, E1.y);
        float h0, h1, h2, h3;
        unpack2(ha, h0, h1); unpack2(hb, h2, h3);
        ha = pack2(fmaxf(h0, 0.0f), fmaxf(h1, 0.0f));
        hb = pack2(fmaxf(h2, 0.0f), fmaxf(h3, 0.0f));
        c0a = fma2(ha, E2.x, c0a);
        c1a = fma2(ha, E2.y, c1a);
        c0b = fma2(hb, E2.x, c0b);
        c1b = fma2(hb, E2.y, c1b);
    }

    float a0, a1, b0, b1, a2, a3, b2, b3;
    unpack2(c0a, a0, a1); unpack2(c1a, b0, b1);
    unpack2(c0b, a2, a3); unpack2(c1b, b2, b3);
    *(float4*)(g_ctx + idx)     = make_float4(a0, b0, a1, b1);
    *(float4*)(g_ctx + idx + 2) = make_float4(a2, b2, a3, b3);
}

// ---------------- K1: posterior + SDE scan (FROZEN numerics, R6) --------
__global__ void __launch_bounds__(128) k_scan(
    const float* __restrict__ ts,
    const float* __restrict__ eps0,const float* __restrict__ bm,
    const float* __restrict__ qw,  const float* __restrict__ qb,
    const float* __restrict__ fw1, const float* __restrict__ fb1,
    const float* __restrict__ fw2, const float* __restrict__ fb2,
    const float* __restrict__ pz0m,const float* __restrict__ pz0ls,
    const float* __restrict__ kap, const float* __restrict__ the,
    const float* __restrict__ sig)
{
    __shared__ ulonglong2 sWA[32];   // {wx pair, wy pair}
    __shared__ ulonglong2 sWB[32];   // {wz pair, wb pair}
    __shared__ float2     sW22[32];  // f_w2 pairs
    __shared__ float      sTs[NT];
    __shared__ float      sred[4];

    const int t = threadIdx.x;
    if (t < 32) {
        int p = t;
        ulonglong2 A, B;
        A.x = pack2(fw1[2*p],       fw1[2*p+1]);        // w_z
        A.y = pack2(fw1[HID+2*p],   fw1[HID+2*p+1]);    // w_c0
        B.x = pack2(fw1[2*HID+2*p], fw1[2*HID+2*p+1]);  // w_c1
        B.y = pack2(fb1[2*p],       fb1[2*p+1]);        // bias
        sWA[p] = A; sWB[p] = B;
        sW22[p] = make_float2(fw2[2*p], fw2[2*p+1]);
    }
    if (t < NT) sTs[t] = ts[t];
    __syncthreads();

    const int b = blockIdx.x * 128 + t;

    const float fb2_s = fb2[0];
    const float kappa = kap[0], theta = the[0], sigma = sig[0];
    const float inv_sig = 1.0f / sigma;
    const float pm = pz0m[0], pls = pz0ls[0];

    float2 c = g_ctx[b];
    float qm  = fmaf(c.x, qw[0], fmaf(c.y, qw[2], qb[0]));
    float qls = fmaf(c.x, qw[1], fmaf(c.y, qw[3], qb[1]));

    float z = qm + expf(qls) * eps0[b];

    float dqm = qm - pm;
    float kl  = pls - qls
              + (expf(2.0f*qls) + dqm*dqm) / (2.0f * expf(2.0f*pls))
              - 0.5f;

    g_zs[b] = z;
    float zmn = z, zmx = z;
    float li = 0.0f;

    float2 cn  = g_ctx[BB + b];
    float  bmv = bm[b];

    #pragma unroll 1
    for (int n = 1; n < NT; n++) {
        const float cc0 = cn.x, cc1 = cn.y, dwe = bmv;
        if (n + 1 < NT) { cn = g_ctx[(n+1)*BB + b]; bmv = bm[n*BB + b]; }
        const float dt = sTs[n] - sTs[n-1];

        const ull zp  = pack2(z,   z);
        const ull c0p = pack2(cc0, cc0);
        const ull c1p = pack2(cc1, cc1);

        float f = fb2_s;
        #pragma unroll
        for (int p = 0; p < 32; p++) {
            ulonglong2 A = sWA[p], B = sWB[p];
            ull d = fma2(c1p, B.x, B.y);
            d = fma2(c0p, A.y, d);
            d = fma2(zp,  A.x, d);
            float h0, h1; unpack2(d, h0, h1);
            float2 w2 = sW22[p];
            f = fmaf(fmaxf(h0, 0.0f), w2.x, f);
            f = fmaf(fmaxf(h1, 0.0f), w2.y, f);
        }

        float u = (f - kappa * (theta - z)) * inv_sig;
        li = fmaf(0.5f * u * u, dt, li);

        float dw = dwe * sqrtf(dt);
        z = fmaf(f, dt, fmaf(sigma, dw, z));

        g_zs[n*BB + b] = z;
        zmn = fminf(zmn, z);
        zmx = fmaxf(zmx, z);
    }

    #pragma unroll
    for (int o = 16; o; o >>= 1) {
        zmn = fminf(zmn, __shfl_xor_sync(0xffffffffu, zmn, o));
        zmx = fmaxf(zmx, __shfl_xor_sync(0xffffffffu, zmx, o));
    }
    if ((t & 31) == 0) {
        atomicMin(&g_zmin_u, f2ord(zmn));
        atomicMax(&g_zmax_u, f2ord(zmx));
    }

    float vli = li, vkl = kl;
    #pragma unroll
    for (int o = 16; o; o >>= 1) {
        vli += __shfl_xor_sync(0xffffffffu, vli, o);
        vkl += __shfl_xor_sync(0xffffffffu, vkl, o);
    }
    int w = t >> 5, l = t & 31;
    if (l == 0) sred[w] = vli;
    __syncthreads();
    if (t == 0) g_part_li[blockIdx.x] = (sred[0]+sred[1])+(sred[2]+sred[3]);
    __syncthreads();
    if (l == 0) sred[w] = vkl;
    __syncthreads();
    if (t == 0) g_part_kl[blockIdx.x] = (sred[0]+sred[1])+(sred[2]+sred[3]);
}

// ---------------- K2: tabulate P(z), 4 lanes cooperate per z-point ------
__global__ void __launch_bounds__(64) k_table(
    const float* __restrict__ pw1, const float* __restrict__ pb1,
    const float* __restrict__ pW2, const float* __restrict__ pb2,
    const float* __restrict__ pw3, const float* __restrict__ pb3)
{
    __shared__ float sw1[HID], sb1[HID], sb2[HID], sw3[HID];
    __shared__ float sW2[HID*HID];
    __shared__ float h1s[ZPB][HID+4];

    const int t = threadIdx.x;   // 64 threads
    { sw1[t]=pw1[t]; sb1[t]=pb1[t]; sb2[t]=pb2[t]; sw3[t]=pw3[t]; }
    for (int i = t; i < HID*HID; i += 64) sW2[i] = pW2[i];
    __syncthreads();

    const int zi    = t >> 2;
    const int lane4 = t & 3;
    const int gz    = blockIdx.x * ZPB + zi;

    float zmin = ord2f(g_zmin_u), zmax = ord2f(g_zmax_u);
    float z = zmin + (zmax - zmin) * ((float)gz / (float)TBL);

    #pragma unroll
    for (int jj = 0; jj < 16; jj++) {
        int j = lane4 * 16 + jj;
        float a = fmaf(z, sw1[j], sb1[j]);
        h1s[zi][j] = fmaxf(a, 0.0f) + __logf(1.0f + __expf(-fabsf(a)));
    }
    __syncthreads();

    const int c0 = lane4 * 16;
    float h2[16];
    #pragma unroll
    for (int k = 0; k < 16; k++) h2[k] = sb2[c0 + k];

    #pragma unroll 8
    for (int j = 0; j < HID; j++) {
        float hj = h1s[zi][j];
        #pragma unroll
        for (int k = 0; k < 16; k++)
            h2[k] = fmaf(hj, sW2[j*HID + c0 + k], h2[k]);
    }

    float acc = 0.0f;
    #pragma unroll
    for (int k = 0; k < 16; k++)
        acc = fmaf(fmaxf(h2[k], 0.0f), sw3[c0 + k], acc);

    acc += __shfl_xor_sync(0xffffffffu, acc, 1);
    acc += __shfl_xor_sync(0xffffffffu, acc, 2);
    if (lane4 == 0 && gz <= TBL) g_table[gz] = acc + pb3[0];
}

// ---------------- K3: table lookup -> _xs + logp + FUSED final ----------
__global__ void __launch_bounds__(256) k_proj(
    const float* __restrict__ xs, const float* __restrict__ nstd,
    float* __restrict__ out)
{
    const int base = (blockIdx.x * 256 + threadIdx.x) * 8;

    float zmin = ord2f(g_zmin_u), zmax = ord2f(g_zmax_u);
    float inv_h = (float)TBL / (zmax - zmin);

    float4 zv0 = *(const float4*)(g_zs + base);
    float4 zv1 = *(const float4*)(g_zs + base + 4);
    float4 xv0 = *(const float4*)(xs + base);
    float4 xv1 = *(const float4*)(xs + base + 4);

    float std = nstd[0];
    float inv_std = 1.0f / std;
    float cterm = -logf(std) - 0.91893853320467274f;

    float zz[8] = {zv0.x, zv0.y, zv0.z, zv0.w, zv1.x, zv1.y, zv1.z, zv1.w};
    float xx[8] = {xv0.x, xv0.y, xv0.z, xv0.w, xv1.x, xv1.y, xv1.z, xv1.w};
    float oo[8];
    float lsum = 0.0f;

    #pragma unroll
    for (int k = 0; k < 8; k++) {
        float tt = (zz[k] - zmin) * inv_h;
        tt = fminf(fmaxf(tt, 0.0f), (float)TBL);
        int   j  = min((int)tt, TBL - 1);
        float fr = tt - (float)j;
        float v0 = g_table[j];
        float v1 = g_table[j+1];
        float xh = fmaf(v1 - v0, fr, v0);
        oo[k] = xh;
        float r = (xx[k] - xh) * inv_std;
        lsum += fmaf(-0.5f, r*r, cterm);
    }

    float2* p = (float2*)(out + 2 + base);
    #pragma unroll
    for (int k = 0; k < 4; k++)
        p[k] = make_float2(oo[2*k], oo[2*k+1]);

    // deterministic block reduce
    float v = lsum;
    #pragma unroll
    for (int o = 16; o; o >>= 1) v += __shfl_xor_sync(0xffffffffu, v, o);
    __shared__ float sred[8];
    __shared__ unsigned sIsLast;
    int w = threadIdx.x >> 5, l = threadIdx.x & 31;
    if (l == 0) sred[w] = v;
    __syncthreads();
    if (threadIdx.x == 0) {
        float s = 0.0f;
        #pragma unroll
        for (int k = 0; k < 8; k++) s += sred[k];
        g_part_logp[blockIdx.x] = s;
        __threadfence();
        unsigned old = atomicAdd(&g_done, 1u);
        sIsLast = (old == (unsigned)(gridDim.x - 1)) ? 1u : 0u;
    }
    __syncthreads();
    if (!sIsLast) return;

    // ---- last block: deterministic final reduction (fixed order) ----
    __shared__ double s[256];
    const int t = threadIdx.x;

    double a = 0.0;
    for (int i = t; i < K3_BLOCKS; i += 256) a += (double)g_part_logp[i];
    s[t] = a; __syncthreads();
    for (int o = 128; o; o >>= 1) { if (t < o) s[t] += s[t+o]; __syncthreads(); }
    double logp_sum = s[0];
    __syncthreads();

    s[t] = (t < K1_BLOCKS) ? (double)g_part_kl[t] : 0.0; __syncthreads();
    for (int o = 128; o; o >>= 1) { if (t < o) s[t] += s[t+o]; __syncthreads(); }
    double kl_sum = s[0];
    __syncthreads();

    s[t] = (t < K1_BLOCKS) ? (double)g_part_li[t] : 0.0; __syncthreads();
    for (int o = 128; o; o >>= 1) { if (t < o) s[t] += s[t+o]; __syncthreads(); }
    double li_sum = s[0];

    if (t == 0) {
        out[0] = (float)(logp_sum / (double)BB);
        out[1] = (float)((kl_sum + li_sum) / (double)BB);
        g_done = 0u;   // reset for next graph replay
    }
}

// ---------------- launch ----------------
extern "C" void kernel_launch(void* const* d_in, const int* in_sizes, int n_in,
                              void* d_out, int out_size)
{
    const float* xs    = (const float*)d_in[0];
    const float* ts    = (const float*)d_in[1];
    const float* nstd  = (const float*)d_in[2];
    const float* eps0  = (const float*)d_in[3];
    const float* bm    = (const float*)d_in[4];
    const float* ew1   = (const float*)d_in[5];
    const float* eb1   = (const float*)d_in[6];
    const float* ew2   = (const float*)d_in[7];
    const float* eb2   = (const float*)d_in[8];
    const float* qw    = (const float*)d_in[9];
    const float* qb    = (const float*)d_in[10];
    const float* fw1   = (const float*)d_in[11];
    const float* fb1   = (const float*)d_in[12];
    const float* fw2   = (const float*)d_in[13];
    const float* fb2   = (const float*)d_in[14];
    const float* pw1   = (const float*)d_in[15];
    const float* pb1   = (const float*)d_in[16];
    const float* pW2   = (const float*)d_in[17];
    const float* pb2   = (const float*)d_in[18];
    const float* pw3   = (const float*)d_in[19];
    const float* pb3   = (const float*)d_in[20];
    const float* pz0m  = (const float*)d_in[21];
    const float* pz0ls = (const float*)d_in[22];
    const float* kap   = (const float*)d_in[23];
    const float* the   = (const float*)d_in[24];
    const float* sig   = (const float*)d_in[25];

    float* out = (float*)d_out;

    // 3-way split so k_scan is the 4th launch (ncu profile slot)
    k_enc<<<KE_SPLIT, 256>>>(xs, ew1, eb1, ew2, eb2, 0);
    k_enc<<<KE_SPLIT, 256>>>(xs, ew1, eb1, ew2, eb2, KE_SPLIT);
    k_enc<<<KE_SPLIT, 256>>>(xs, ew1, eb1, ew2, eb2, 2*KE_SPLIT);
    k_scan<<<K1_BLOCKS, 128>>>(ts, eps0, bm, qw, qb,
                               fw1, fb1, fw2, fb2,
                               pz0m, pz0ls, kap, the, sig);
    k_table<<<TBL_BLOCKS, 64>>>(pw1, pb1, pW2, pb2, pw3, pb3);
    k_proj<<<K3_BLOCKS, 256>>>(xs, nstd, out);
}